// round 1
// baseline (speedup 1.0000x reference)
#include <cuda_runtime.h>
#include <stdint.h>

typedef unsigned int u32;
typedef unsigned long long u64;
typedef unsigned char u8;

#define N_ANCH 262144
#define N_CLS  80
#define TOPK   1024
#define BND_CAP 4096
#define FULLM 0xFFFFFFFFu

// ---------------- scratch (static device globals; no allocation) ----------------
__device__ u32 g_key[N_ANCH];          // sortable key of masked conf
__device__ u8  g_label[N_ANCH];        // argmax class
__device__ u32 g_hist[3][256];
__device__ u32 g_state[2];             // [0]=prefix, [1]=count strictly above
__device__ u32 g_cnt[2];               // [0]=above counter, [1]=boundary counter
__device__ u64 g_sel[TOPK];
__device__ u64 g_bnd[BND_CAP];
__device__ float4 g_off[TOPK];
__device__ float  g_area[TOPK];
__device__ float4 g_tbox[TOPK];
__device__ float  g_tconf[TOPK];
__device__ float  g_tlab[TOPK];
__device__ u32 g_valid[TOPK / 32];
__device__ u32 g_sup[TOPK * TOPK / 32];       // 128KB suppression bitmask
__device__ __align__(16) u8 g_rownz[TOPK];
__device__ u32 g_keep[TOPK / 32];

// ---------------- kernels ----------------

__global__ void k_zero() {
    int t = blockIdx.x * blockDim.x + threadIdx.x;
    if (t < 768) ((u32*)g_hist)[t] = 0u;
    if (t < 2) g_cnt[t] = 0u;
}

// one warp per anchor: conf=max, label=argmax(first max), write sortable key
__global__ void k_argmax(const float* __restrict__ scores) {
    int warp = (blockIdx.x * blockDim.x + threadIdx.x) >> 5;
    int lane = threadIdx.x & 31;
    if (warp >= N_ANCH) return;
    const float* row = scores + (size_t)warp * N_CLS;
    float v = row[lane];
    int   c = lane;
    float v1 = row[32 + lane];
    if (v1 > v) { v = v1; c = lane + 32; }
    if (lane < 16) {
        float v2 = row[64 + lane];
        if (v2 > v) { v = v2; c = lane + 64; }
    }
    #pragma unroll
    for (int off = 16; off; off >>= 1) {
        float ov = __shfl_down_sync(FULLM, v, off);
        int   oc = __shfl_down_sync(FULLM, c, off);
        if (ov > v || (ov == v && oc < c)) { v = ov; c = oc; }
    }
    if (lane == 0) {
        float m = (v >= 0.5f) ? v : -1.0f;
        u32 b = __float_as_uint(m);
        u32 k = (b & 0x80000000u) ? ~b : (b | 0x80000000u);
        g_key[warp]   = k;
        g_label[warp] = (u8)c;
    }
}

// 8-bit digit histogram over keys matching current prefix (smem + warp-agg atomics)
template <int ROUND>
__global__ void k_hist() {
    __shared__ u32 sh[256];
    int t = threadIdx.x;
    if (t < 256) sh[t] = 0u;
    __syncthreads();
    u32 prefix = (ROUND == 1) ? 0u : g_state[0];
    int stride = blockDim.x * gridDim.x;
    for (int i = blockIdx.x * blockDim.x + t; i < N_ANCH; i += stride) {
        u32 k = g_key[i];
        bool pred; u32 bin;
        if (ROUND == 1)      { pred = true;                    bin = k >> 24; }
        else if (ROUND == 2) { pred = ((k >> 24) == prefix);   bin = (k >> 16) & 255u; }
        else                 { pred = ((k >> 16) == prefix);   bin = (k >> 8)  & 255u; }
        u32 act = __ballot_sync(FULLM, pred);
        if (pred) {
            u32 peers = __match_any_sync(act, bin);
            int leader = __ffs(peers) - 1;
            if ((int)(threadIdx.x & 31) == leader)
                atomicAdd(&sh[bin], (u32)__popc(peers));
        }
    }
    __syncthreads();
    if (t < 256 && sh[t]) atomicAdd(&g_hist[ROUND - 1][t], sh[t]);
}

// parallel suffix-scan over 256 bins; pick boundary digit
template <int ROUND>
__global__ void k_scan() {
    __shared__ u32 suf[256];
    int d = threadIdx.x;
    suf[d] = g_hist[ROUND - 1][d];
    __syncthreads();
    // Hillis-Steele suffix sum (inclusive)
    for (int off = 1; off < 256; off <<= 1) {
        u32 v = (d + off < 256) ? suf[d + off] : 0u;
        __syncthreads();
        suf[d] += v;
        __syncthreads();
    }
    u32 A      = (ROUND == 1) ? 0u : g_state[1];
    u32 prefix = (ROUND == 1) ? 0u : g_state[0];
    u32 s_incl = suf[d];
    u32 s_excl = (d < 255) ? suf[d + 1] : 0u;
    if (A + s_excl < (u32)TOPK && A + s_incl >= (u32)TOPK) {
        g_state[0] = (prefix << 8) | (u32)d;
        g_state[1] = A + s_excl;
    }
}

__global__ void k_gather() {
    int i = blockIdx.x * blockDim.x + threadIdx.x;
    if (i >= N_ANCH) return;
    u32 k = g_key[i];
    u32 P24 = g_state[0];
    u32 t = k >> 8;
    u64 key64 = ((u64)k << 32) | (u64)(FULLM - (u32)i);
    if (t > P24) {
        u32 p = atomicAdd(&g_cnt[0], 1u);
        if (p < TOPK) g_sel[p] = key64;
    } else if (t == P24) {
        u32 p = atomicAdd(&g_cnt[1], 1u);
        if (p < BND_CAP) g_bnd[p] = key64;
    }
}

__device__ __forceinline__ void bitonic_desc(u64* s, int n, int tid, int nthr) {
    for (int k = 2; k <= n; k <<= 1) {
        for (int j = k >> 1; j > 0; j >>= 1) {
            for (int i = tid; i < n; i += nthr) {
                int ixj = i ^ j;
                if (ixj > i) {
                    u64 a = s[i], b = s[ixj];
                    bool up = (i & k) != 0;            // ascending segment
                    bool sw = up ? (a > b) : (a < b);  // overall descending
                    if (sw) { s[i] = b; s[ixj] = a; }
                }
            }
            __syncthreads();
        }
    }
}

__global__ __launch_bounds__(1024) void k_finalize(const float4* __restrict__ boxes) {
    __shared__ u64 s[BND_CAP];
    __shared__ float smax[32];
    int tid = threadIdx.x;
    u32 A  = min(g_cnt[0], (u32)TOPK);
    u32 nb = min(g_cnt[1], (u32)BND_CAP);
    for (int i = tid; i < BND_CAP; i += 1024) s[i] = (i < (int)nb) ? g_bnd[i] : 0ull;
    __syncthreads();
    bitonic_desc(s, BND_CAP, tid, 1024);
    int need = TOPK - (int)A;
    if (tid < need) g_sel[A + tid] = s[tid];
    __syncthreads();
    // sort final 1024 by (conf desc, idx asc)
    s[tid] = g_sel[tid];
    __syncthreads();
    bitonic_desc(s, TOPK, tid, 1024);
    u64 kk = s[tid];
    u32 key32 = (u32)(kk >> 32);
    u32 idx = FULLM - (u32)(kk & FULLM);
    u32 bits = (key32 & 0x80000000u) ? (key32 ^ 0x80000000u) : ~key32;
    float conf = __uint_as_float(bits);
    float lab = (float)(int)g_label[idx];
    float4 bx = boxes[idx];
    // block max over all coords
    float mv = fmaxf(fmaxf(bx.x, bx.y), fmaxf(bx.z, bx.w));
    #pragma unroll
    for (int off = 16; off; off >>= 1)
        mv = fmaxf(mv, __shfl_down_sync(FULLM, mv, off));
    if ((tid & 31) == 0) smax[tid >> 5] = mv;
    __syncthreads();
    if (tid < 32) {
        float m2 = smax[tid];
        #pragma unroll
        for (int off = 16; off; off >>= 1)
            m2 = fmaxf(m2, __shfl_down_sync(FULLM, m2, off));
        if (tid == 0) smax[0] = m2;
    }
    __syncthreads();
    float mc = __fadd_rn(smax[0], 1.0f);
    float t = __fmul_rn(lab, mc);
    float ox1 = __fadd_rn(bx.x, t), oy1 = __fadd_rn(bx.y, t);
    float ox2 = __fadd_rn(bx.z, t), oy2 = __fadd_rn(bx.w, t);
    g_off[tid]  = make_float4(ox1, oy1, ox2, oy2);
    g_area[tid] = __fmul_rn(__fsub_rn(ox2, ox1), __fsub_rn(oy2, oy1));
    g_tbox[tid] = bx;
    g_tconf[tid] = conf;
    g_tlab[tid]  = lab;
    u32 vb = __ballot_sync(FULLM, conf >= 0.5f);
    if ((tid & 31) == 0) g_valid[tid >> 5] = vb;
}

// suppression bitmask: warp = row i, lane = 32-bit word of columns
__global__ void k_iou() {
    __shared__ float4 soff[TOPK];
    __shared__ float sarea[TOPK];
    int tid = threadIdx.x;  // 256
    for (int i = tid; i < TOPK; i += 256) { soff[i] = g_off[i]; sarea[i] = g_area[i]; }
    __syncthreads();
    int wid = tid >> 5, lane = tid & 31;
    int i = blockIdx.x * 8 + wid;
    float4 bi = soff[i];
    float  ai = sarea[i];
    u32 word = 0;
    int jbase = lane * 32;
    #pragma unroll 4
    for (int jj = 0; jj < 32; jj++) {
        int j = jbase + jj;
        float4 bj = soff[j];
        float lx = fmaxf(bi.x, bj.x), ly = fmaxf(bi.y, bj.y);
        float rx = fminf(bi.z, bj.z), ry = fminf(bi.w, bj.w);
        float wx = fmaxf(__fsub_rn(rx, lx), 0.0f);
        float wy = fmaxf(__fsub_rn(ry, ly), 0.0f);
        float inter = __fmul_rn(wx, wy);
        float un = __fsub_rn(__fadd_rn(ai, sarea[j]), inter);
        float iou = __fdiv_rn(inter, fmaxf(un, 1e-9f));
        if (j > i && iou > 0.6f) word |= (1u << jj);
    }
    g_sup[i * 32 + lane] = word;
    bool nz = __any_sync(FULLM, word != 0u);
    if (lane == 0) g_rownz[i] = nz ? (u8)1 : (u8)0;
}

// single-warp exact sequential greedy NMS, skipping all-zero rows
__global__ void k_nms() {
    int lane = threadIdx.x;  // 32
    u32 kw = g_valid[lane];
    u32 nz = 0;
    const u32* rp = (const u32*)g_rownz;
    #pragma unroll
    for (int q = 0; q < 8; q++) {
        u32 v = rp[lane * 8 + q];
        u32 bitsv = (v & 1u) | (((v >> 8) & 1u) << 1) |
                    (((v >> 16) & 1u) << 2) | (((v >> 24) & 1u) << 3);
        nz |= bitsv << (4 * q);
    }
    for (int g = 0; g < 32; g++) {
        u32 nzg = __shfl_sync(FULLM, nz, g);   // uniform
        if (!nzg) continue;
        u32 kwg = __shfl_sync(FULLM, kw, g);
        u32 act = nzg & kwg;
        while (act) {
            int b = __ffs(act) - 1;
            int i = g * 32 + b;
            kw &= ~g_sup[i * 32 + lane];
            kwg = __shfl_sync(FULLM, kw, g);
            u32 maskAbove = (b == 31) ? 0u : (FULLM << (b + 1));
            act = nzg & kwg & maskAbove;
        }
    }
    g_keep[lane] = kw;
}

__global__ void k_out(float* __restrict__ out) {
    int k = blockIdx.x * blockDim.x + threadIdx.x;
    if (k >= TOPK) return;
    bool kp = (g_keep[k >> 5] >> (k & 31)) & 1u;
    float4 b = g_tbox[k];
    float* o = out + k * 6;
    if (kp) {
        o[0] = b.x; o[1] = b.y; o[2] = b.z; o[3] = b.w;
        o[4] = g_tconf[k]; o[5] = g_tlab[k];
    } else {
        o[0] = 0.f; o[1] = 0.f; o[2] = 0.f; o[3] = 0.f; o[4] = 0.f; o[5] = 0.f;
    }
}

// ---------------- launch ----------------
extern "C" void kernel_launch(void* const* d_in, const int* in_sizes, int n_in,
                              void* d_out, int out_size) {
    const float* boxes  = (const float*)d_in[0];
    const float* scores = (const float*)d_in[1];
    if (in_sizes[0] != N_ANCH * 4) {  // defensive input-order check
        boxes  = (const float*)d_in[1];
        scores = (const float*)d_in[0];
    }
    float* out = (float*)d_out;

    k_zero<<<4, 256>>>();
    k_argmax<<<(N_ANCH * 32) / 256, 256>>>(scores);
    k_hist<1><<<256, 256>>>();
    k_scan<1><<<1, 256>>>();
    k_hist<2><<<256, 256>>>();
    k_scan<2><<<1, 256>>>();
    k_hist<3><<<256, 256>>>();
    k_scan<3><<<1, 256>>>();
    k_gather<<<N_ANCH / 256, 256>>>();
    k_finalize<<<1, 1024>>>((const float4*)boxes);
    k_iou<<<TOPK / 8, 256>>>();
    k_nms<<<1, 32>>>();
    k_out<<<TOPK / 256, 256>>>(out);
}

// round 2
// speedup vs baseline: 1.2686x; 1.2686x over previous
#include <cuda_runtime.h>
#include <stdint.h>

typedef unsigned int u32;
typedef unsigned long long u64;
typedef unsigned char u8;

#define N_ANCH 262144
#define N_CLS  80
#define TOPK   1024
#define BND_CAP 4096
#define FULLM 0xFFFFFFFFu
#define K1_BLOCKS 1184

// ---------------- scratch (static device globals; no allocation) ----------------
__device__ u32 g_key[N_ANCH];
__device__ u8  g_label[N_ANCH];
__device__ u32 g_hist[3][256];
__device__ u32 g_state[2];             // [0]=prefix, [1]=count strictly above
__device__ u32 g_cnt[2];               // [0]=above counter, [1]=boundary counter
__device__ u32 g_tick[8];              // last-block tickets (self-resetting)
__device__ u64 g_sel[TOPK];
__device__ u64 g_bnd[BND_CAP];
__device__ float4 g_off[TOPK];
__device__ float  g_area[TOPK];
__device__ float4 g_tbox[TOPK];
__device__ float  g_tconf[TOPK];
__device__ float  g_tlab[TOPK];
__device__ u32 g_valid[TOPK / 32];
__device__ u32 g_sup[TOPK * TOPK / 32];
__device__ __align__(16) u8 g_rownz[TOPK];

// ---------------- helpers ----------------

// 256-bin suffix scan + boundary pick; requires blockDim.x == 256
__device__ void scan256(const u32* hist, u32* suf, u32 prefix, u32 A) {
    int d = threadIdx.x;
    suf[d] = hist[d];
    __syncthreads();
    for (int off = 1; off < 256; off <<= 1) {
        u32 v = (d + off < 256) ? suf[d + off] : 0u;
        __syncthreads();
        suf[d] += v;
        __syncthreads();
    }
    u32 s_incl = suf[d];
    u32 s_excl = (d < 255) ? suf[d + 1] : 0u;
    if (A + s_excl < (u32)TOPK && A + s_incl >= (u32)TOPK) {
        g_state[0] = (prefix << 8) | (u32)d;
        g_state[1] = A + s_excl;
    }
}

__device__ __forceinline__ void bitonic_desc(u64* s, int n, int tid, int nthr) {
    for (int k = 2; k <= n; k <<= 1) {
        for (int j = k >> 1; j > 0; j >>= 1) {
            for (int i = tid; i < n; i += nthr) {
                int ixj = i ^ j;
                if (ixj > i) {
                    u64 a = s[i], b = s[ixj];
                    bool up = (i & k) != 0;            // ascending segment
                    bool sw = up ? (a > b) : (a < b);  // overall descending
                    if (sw) { s[i] = b; s[ixj] = a; }
                }
            }
            __syncthreads();
        }
    }
}

// ---------------- K1: argmax + hist round 1 + last-block scan ----------------
__global__ __launch_bounds__(256) void k1_argmax(const float* __restrict__ scores) {
    __shared__ u32 sh[256];
    __shared__ u32 sLast;
    int t = threadIdx.x, lane = t & 31;
    sh[t] = 0u;
    __syncthreads();
    int gwarp = (blockIdx.x * 256 + t) >> 5;
    int nwarp = (gridDim.x * 256) >> 5;
    for (int row = gwarp; row < N_ANCH; row += nwarp) {
        const float* r = scores + (size_t)row * N_CLS;
        float v = r[lane];
        int   c = lane;
        float v1 = r[32 + lane];
        if (v1 > v) { v = v1; c = lane + 32; }
        if (lane < 16) {
            float v2 = r[64 + lane];
            if (v2 > v) { v = v2; c = lane + 64; }
        }
        #pragma unroll
        for (int off = 16; off; off >>= 1) {
            float ov = __shfl_down_sync(FULLM, v, off);
            int   oc = __shfl_down_sync(FULLM, c, off);
            if (ov > v || (ov == v && oc < c)) { v = ov; c = oc; }
        }
        if (lane == 0) {
            float m = (v >= 0.5f) ? v : -1.0f;
            u32 b = __float_as_uint(m);
            u32 k = (b & 0x80000000u) ? ~b : (b | 0x80000000u);
            g_key[row]   = k;
            g_label[row] = (u8)c;
            atomicAdd(&sh[k >> 24], 1u);
        }
    }
    __syncthreads();
    if (sh[t]) atomicAdd(&g_hist[0][t], sh[t]);
    __threadfence();
    if (t == 0) sLast = (atomicAdd(&g_tick[0], 1u) == gridDim.x - 1) ? 1u : 0u;
    __syncthreads();
    if (!sLast) return;
    if (t == 0) g_tick[0] = 0u;
    scan256(g_hist[0], sh, 0u, 0u);
    g_hist[0][t] = 0u;   // self-clean for next replay
}

// ---------------- K2/K3: hist round + last-block scan ----------------
template <int ROUND>
__global__ __launch_bounds__(256) void k_histscan() {
    __shared__ u32 sh[256];
    __shared__ u32 sLast;
    int t = threadIdx.x;
    sh[t] = 0u;
    __syncthreads();
    u32 prefix = g_state[0];
    u32 A      = g_state[1];
    int stride = 256 * gridDim.x;
    for (int i = blockIdx.x * 256 + t; i < N_ANCH; i += stride) {
        u32 k = g_key[i];
        bool pred; u32 bin;
        if (ROUND == 2) { pred = ((k >> 24) == prefix); bin = (k >> 16) & 255u; }
        else            { pred = ((k >> 16) == prefix); bin = (k >> 8)  & 255u; }
        u32 act = __ballot_sync(FULLM, pred);
        if (pred) {
            u32 peers = __match_any_sync(act, bin);
            int leader = __ffs(peers) - 1;
            if ((t & 31) == leader) atomicAdd(&sh[bin], (u32)__popc(peers));
        }
    }
    __syncthreads();
    if (sh[t]) atomicAdd(&g_hist[ROUND - 1][t], sh[t]);
    __threadfence();
    if (t == 0) sLast = (atomicAdd(&g_tick[ROUND - 1], 1u) == gridDim.x - 1) ? 1u : 0u;
    __syncthreads();
    if (!sLast) return;
    if (t == 0) g_tick[ROUND - 1] = 0u;
    scan256(g_hist[ROUND - 1], sh, prefix, A);
    g_hist[ROUND - 1][t] = 0u;   // self-clean
}

// ---------------- K4: gather + last-block finalize (sort + prep) ----------------
__global__ __launch_bounds__(1024) void k4_gather_finalize(const float4* __restrict__ boxes) {
    __shared__ u64 s[BND_CAP];
    __shared__ float smax[32];
    __shared__ u32 sLast;
    int tid = threadIdx.x;
    u32 P24 = g_state[0];
    int i = blockIdx.x * 1024 + tid;
    if (i < N_ANCH) {
        u32 k = g_key[i];
        u32 tv = k >> 8;
        u64 key64 = ((u64)k << 32) | (u64)(FULLM - (u32)i);
        if (tv > P24) {
            u32 p = atomicAdd(&g_cnt[0], 1u);
            if (p < TOPK) g_sel[p] = key64;
        } else if (tv == P24) {
            u32 p = atomicAdd(&g_cnt[1], 1u);
            if (p < BND_CAP) g_bnd[p] = key64;
        }
    }
    __threadfence();
    if (tid == 0) sLast = (atomicAdd(&g_tick[3], 1u) == gridDim.x - 1) ? 1u : 0u;
    __syncthreads();
    if (!sLast) return;
    u32 A  = min(g_cnt[0], (u32)TOPK);
    u32 nb = min(g_cnt[1], (u32)BND_CAP);
    __syncthreads();
    if (tid == 0) { g_tick[3] = 0u; g_cnt[0] = 0u; g_cnt[1] = 0u; }   // self-clean
    int need = TOPK - (int)A;
    int n = 1024;
    while (n < (int)nb) n <<= 1;   // adaptive pow2 size (<= BND_CAP)
    for (int j = tid; j < n; j += 1024) s[j] = (j < (int)nb) ? g_bnd[j] : 0ull;
    __syncthreads();
    bitonic_desc(s, n, tid, 1024);
    if (tid < need) g_sel[A + tid] = s[tid];
    __syncthreads();
    // final sort of the 1024 selected by (conf desc, idx asc)
    s[tid] = g_sel[tid];
    __syncthreads();
    bitonic_desc(s, TOPK, tid, 1024);
    u64 kk = s[tid];
    u32 key32 = (u32)(kk >> 32);
    u32 idx = FULLM - (u32)(kk & FULLM);
    u32 bits = (key32 & 0x80000000u) ? (key32 ^ 0x80000000u) : ~key32;
    float conf = __uint_as_float(bits);
    float lab = (float)(int)g_label[idx];
    float4 bx = boxes[idx];
    // block max over all coords
    float mv = fmaxf(fmaxf(bx.x, bx.y), fmaxf(bx.z, bx.w));
    #pragma unroll
    for (int off = 16; off; off >>= 1)
        mv = fmaxf(mv, __shfl_down_sync(FULLM, mv, off));
    if ((tid & 31) == 0) smax[tid >> 5] = mv;
    __syncthreads();
    if (tid < 32) {
        float m2 = smax[tid];
        #pragma unroll
        for (int off = 16; off; off >>= 1)
            m2 = fmaxf(m2, __shfl_down_sync(FULLM, m2, off));
        if (tid == 0) smax[0] = m2;
    }
    __syncthreads();
    float mc = __fadd_rn(smax[0], 1.0f);
    float tt = __fmul_rn(lab, mc);
    float ox1 = __fadd_rn(bx.x, tt), oy1 = __fadd_rn(bx.y, tt);
    float ox2 = __fadd_rn(bx.z, tt), oy2 = __fadd_rn(bx.w, tt);
    g_off[tid]  = make_float4(ox1, oy1, ox2, oy2);
    g_area[tid] = __fmul_rn(__fsub_rn(ox2, ox1), __fsub_rn(oy2, oy1));
    g_tbox[tid] = bx;
    g_tconf[tid] = conf;
    g_tlab[tid]  = lab;
    u32 vb = __ballot_sync(FULLM, conf >= 0.5f);
    if ((tid & 31) == 0) g_valid[tid >> 5] = vb;
}

// ---------------- K5: IoU bitmask + last-block NMS + output ----------------
__global__ __launch_bounds__(256) void k5_iou_nms_out(float* __restrict__ out) {
    __shared__ float4 soff[TOPK];
    __shared__ float sarea[TOPK];
    __shared__ u32 skeep[32];
    __shared__ u32 sLast;
    int tid = threadIdx.x;  // 256
    for (int i = tid; i < TOPK; i += 256) { soff[i] = g_off[i]; sarea[i] = g_area[i]; }
    __syncthreads();
    int wid = tid >> 5, lane = tid & 31;
    int i = blockIdx.x * 8 + wid;
    float4 bi = soff[i];
    float  ai = sarea[i];
    u32 word = 0;
    int jbase = lane * 32;
    #pragma unroll 4
    for (int jj = 0; jj < 32; jj++) {
        int j = jbase + jj;
        float4 bj = soff[j];
        float lx = fmaxf(bi.x, bj.x), ly = fmaxf(bi.y, bj.y);
        float rx = fminf(bi.z, bj.z), ry = fminf(bi.w, bj.w);
        float wx = fmaxf(__fsub_rn(rx, lx), 0.0f);
        float wy = fmaxf(__fsub_rn(ry, ly), 0.0f);
        float inter = __fmul_rn(wx, wy);
        float un = __fsub_rn(__fadd_rn(ai, sarea[j]), inter);
        float iou = __fdiv_rn(inter, fmaxf(un, 1e-9f));
        if (j > i && iou > 0.6f) word |= (1u << jj);
    }
    g_sup[i * 32 + lane] = word;
    bool nzr = __any_sync(FULLM, word != 0u);
    if (lane == 0) g_rownz[i] = nzr ? (u8)1 : (u8)0;
    __threadfence();
    if (tid == 0) sLast = (atomicAdd(&g_tick[4], 1u) == gridDim.x - 1) ? 1u : 0u;
    __syncthreads();
    if (!sLast) return;
    if (tid == 0) g_tick[4] = 0u;
    // --- single-warp exact sequential greedy NMS (warp 0) ---
    if (tid < 32) {
        u32 kw = g_valid[tid];
        u32 nz = 0;
        const u32* rp = (const u32*)g_rownz;
        #pragma unroll
        for (int q = 0; q < 8; q++) {
            u32 v = rp[tid * 8 + q];
            u32 bitsv = (v & 1u) | (((v >> 8) & 1u) << 1) |
                        (((v >> 16) & 1u) << 2) | (((v >> 24) & 1u) << 3);
            nz |= bitsv << (4 * q);
        }
        for (int g = 0; g < 32; g++) {
            u32 nzg = __shfl_sync(FULLM, nz, g);
            if (!nzg) continue;
            u32 kwg = __shfl_sync(FULLM, kw, g);
            u32 act = nzg & kwg;
            while (act) {
                int b = __ffs(act) - 1;
                int r = g * 32 + b;
                kw &= ~g_sup[r * 32 + tid];
                kwg = __shfl_sync(FULLM, kw, g);
                u32 maskAbove = (b == 31) ? 0u : (FULLM << (b + 1));
                act = nzg & kwg & maskAbove;
            }
        }
        skeep[tid] = kw;
    }
    __syncthreads();
    // --- output: 256 threads x 4 rows ---
    #pragma unroll
    for (int q = 0; q < 4; q++) {
        int k = tid * 4 + q;
        bool kp = (skeep[k >> 5] >> (k & 31)) & 1u;
        float2* o = (float2*)(out + (size_t)k * 6);
        if (kp) {
            float4 b = g_tbox[k];
            o[0] = make_float2(b.x, b.y);
            o[1] = make_float2(b.z, b.w);
            o[2] = make_float2(g_tconf[k], g_tlab[k]);
        } else {
            float2 z = make_float2(0.f, 0.f);
            o[0] = z; o[1] = z; o[2] = z;
        }
    }
}

// ---------------- launch ----------------
extern "C" void kernel_launch(void* const* d_in, const int* in_sizes, int n_in,
                              void* d_out, int out_size) {
    const float* boxes  = (const float*)d_in[0];
    const float* scores = (const float*)d_in[1];
    if (in_sizes[0] != N_ANCH * 4) {  // defensive input-order check
        boxes  = (const float*)d_in[1];
        scores = (const float*)d_in[0];
    }
    float* out = (float*)d_out;

    k1_argmax<<<K1_BLOCKS, 256>>>(scores);
    k_histscan<2><<<256, 256>>>();
    k_histscan<3><<<256, 256>>>();
    k4_gather_finalize<<<256, 1024>>>((const float4*)boxes);
    k5_iou_nms_out<<<128, 256>>>(out);
}

// round 3
// speedup vs baseline: 1.4246x; 1.1230x over previous
#include <cuda_runtime.h>
#include <stdint.h>

typedef unsigned int u32;
typedef unsigned long long u64;
typedef unsigned char u8;

#define N_ANCH 262144
#define N_CLS  80
#define TOPK   1024
#define BND_CAP 4096
#define FULLM 0xFFFFFFFFu

// ---------------- scratch (static device globals; no allocation) ----------------
__device__ u32 g_key[N_ANCH];
__device__ u8  g_label[N_ANCH];
__device__ u32 g_hist1[4096];
__device__ u32 g_hist2[4096];
__device__ u32 g_state[2];             // [0]=prefix, [1]=A (count strictly above)
__device__ u32 g_cnt[2];               // [0]=above counter, [1]=boundary counter
__device__ u32 g_tick[4];              // last-block tickets (self-resetting)
__device__ u64 g_above[TOPK];
__device__ u64 g_bnd[BND_CAP];
__device__ u32 g_maxc;                 // float bits of max coord (coords >= 0)
__device__ float4 g_tbox[TOPK];
__device__ float  g_tconf[TOPK];
__device__ float  g_tlab[TOPK];
__device__ u32 g_sup[TOPK * TOPK / 32];
__device__ __align__(16) u8 g_rownz[TOPK];

// ---------------- helpers ----------------

// 4096-bin suffix scan + boundary pick; blockDim.x == 256. Each thread owns 16 bins.
__device__ void scan4096(const u32* hist, u32 prefix, u32 A) {
    __shared__ u32 suf[256];
    int t = threadIdx.x;
    u32 base = t * 16;
    u32 sincl[16];
    u32 s = 0;
    #pragma unroll
    for (int q = 15; q >= 0; q--) { s += hist[base + q]; sincl[q] = s; }
    suf[t] = s;
    __syncthreads();
    for (int off = 1; off < 256; off <<= 1) {
        u32 x = (t + off < 256) ? suf[t + off] : 0u;
        __syncthreads();
        suf[t] += x;
        __syncthreads();
    }
    u32 grp_excl = (t < 255) ? suf[t + 1] : 0u;   // sum over groups strictly right
    #pragma unroll
    for (int q = 0; q < 16; q++) {
        u32 incl = sincl[q] + grp_excl;
        u32 excl = ((q < 15) ? sincl[q + 1] : 0u) + grp_excl;
        if (A + excl < (u32)TOPK && A + incl >= (u32)TOPK) {
            g_state[0] = (prefix << 12) | (base + q);
            g_state[1] = A + excl;
        }
    }
}

// ---------------- K1: argmax + 12-bit hist round 1 + last-block scan ----------------
__global__ __launch_bounds__(256) void k1_argmax(const float* __restrict__ scores) {
    __shared__ u32 sh[4096];
    __shared__ u32 sLast;
    int t = threadIdx.x, lane = t & 31;
    for (int i = t; i < 4096; i += 256) sh[i] = 0u;
    __syncthreads();
    int gwarp = (blockIdx.x * 256 + t) >> 5;
    int nwarp = (gridDim.x * 256) >> 5;
    u32 runBin = FULLM, runCnt = 0;       // lane0 run-length aggregation
    for (int row = gwarp; row < N_ANCH; row += nwarp) {
        const float* r = scores + (size_t)row * N_CLS;
        float v = r[lane];
        int   c = lane;
        float v1 = r[32 + lane];
        if (v1 > v) { v = v1; c = lane + 32; }
        if (lane < 16) {
            float v2 = r[64 + lane];
            if (v2 > v) { v = v2; c = lane + 64; }
        }
        #pragma unroll
        for (int off = 16; off; off >>= 1) {
            float ov = __shfl_down_sync(FULLM, v, off);
            int   oc = __shfl_down_sync(FULLM, c, off);
            if (ov > v || (ov == v && oc < c)) { v = ov; c = oc; }
        }
        if (lane == 0) {
            float m = (v >= 0.5f) ? v : -1.0f;
            u32 b = __float_as_uint(m);
            u32 k = (b & 0x80000000u) ? ~b : (b | 0x80000000u);
            g_key[row]   = k;
            g_label[row] = (u8)c;
            u32 bin = k >> 20;
            if (bin == runBin) runCnt++;
            else {
                if (runCnt) atomicAdd(&sh[runBin], runCnt);
                runBin = bin; runCnt = 1;
            }
        }
    }
    if (lane == 0 && runCnt) atomicAdd(&sh[runBin], runCnt);
    __syncthreads();
    for (int i = t; i < 4096; i += 256) if (sh[i]) atomicAdd(&g_hist1[i], sh[i]);
    __threadfence();
    if (t == 0) sLast = (atomicAdd(&g_tick[0], 1u) == gridDim.x - 1) ? 1u : 0u;
    __syncthreads();
    if (!sLast) return;
    if (t == 0) g_tick[0] = 0u;
    scan4096(g_hist1, 0u, 0u);
    for (int i = t; i < 4096; i += 256) g_hist1[i] = 0u;   // self-clean
}

// ---------------- K2: 12-bit hist round 2 (within prefix) + last-block scan ----------------
__global__ __launch_bounds__(256) void k2_hist() {
    __shared__ u32 sh[4096];
    __shared__ u32 sLast;
    int t = threadIdx.x;
    for (int i = t; i < 4096; i += 256) sh[i] = 0u;
    __syncthreads();
    u32 P12 = g_state[0];
    u32 A   = g_state[1];
    int stride = 256 * gridDim.x;
    for (int i = blockIdx.x * 256 + t; i < N_ANCH; i += stride) {
        u32 k = g_key[i];
        bool pred = ((k >> 20) == P12);
        u32 bin = (k >> 8) & 4095u;
        u32 act = __ballot_sync(FULLM, pred);
        if (pred) {
            u32 peers = __match_any_sync(act, bin);
            int leader = __ffs(peers) - 1;
            if ((t & 31) == leader) atomicAdd(&sh[bin], (u32)__popc(peers));
        }
    }
    __syncthreads();
    for (int i = t; i < 4096; i += 256) if (sh[i]) atomicAdd(&g_hist2[i], sh[i]);
    __threadfence();
    if (t == 0) sLast = (atomicAdd(&g_tick[1], 1u) == gridDim.x - 1) ? 1u : 0u;
    __syncthreads();
    if (!sLast) return;
    if (t == 0) g_tick[1] = 0u;
    scan4096(g_hist2, P12, A);
    for (int i = t; i < 4096; i += 256) g_hist2[i] = 0u;   // self-clean
}

// ---------------- K3: gather above / boundary candidates ----------------
__global__ __launch_bounds__(256) void k3_gather() {
    int i = blockIdx.x * 256 + threadIdx.x;
    if (i >= N_ANCH) return;
    u32 k = g_key[i];
    u32 P24 = g_state[0];
    u32 tv = k >> 8;
    if (tv < P24) return;
    u64 key64 = ((u64)k << 32) | (u64)(FULLM - (u32)i);
    if (tv > P24) {
        u32 p = atomicAdd(&g_cnt[0], 1u);
        if (p < TOPK) g_above[p] = key64;
    } else {
        u32 p = atomicAdd(&g_cnt[1], 1u);
        if (p < BND_CAP) g_bnd[p] = key64;
    }
}

// ---------------- K4: warp-per-candidate rank + scatter (replaces sorts) ----------------
__global__ __launch_bounds__(256) void k4_rank(const float4* __restrict__ boxes) {
    int w = (blockIdx.x * 256 + threadIdx.x) >> 5;
    int lane = threadIdx.x & 31;
    u32 A  = min(g_cnt[0], (u32)TOPK);
    u32 nb = min(g_cnt[1], (u32)BND_CAP);
    const u64* list;
    u32 n, basepos, me;
    if (w < (int)A)            { list = g_above; n = A;  me = (u32)w;       basepos = 0u; }
    else if (w < (int)(A + nb)){ list = g_bnd;   n = nb; me = (u32)w - A;   basepos = A;  }
    else return;
    u64 myk = list[me];
    u32 rank = 0;
    for (u32 j0 = 0; j0 < n; j0 += 32) {
        u32 j = j0 + lane;
        u64 other = (j < n) ? list[j] : 0ull;
        rank += (u32)__popc(__ballot_sync(FULLM, other > myk));
    }
    u32 pos = basepos + rank;          // unique: keys strictly ordered (idx tiebreak)
    if (pos >= (u32)TOPK) return;      // boundary losers
    if (lane == 0) {
        u32 key32 = (u32)(myk >> 32);
        u32 idx = FULLM - (u32)(myk & FULLM);
        u32 bits = (key32 & 0x80000000u) ? (key32 ^ 0x80000000u) : ~key32;
        float conf = __uint_as_float(bits);
        float4 bx = boxes[idx];
        g_tbox[pos]  = bx;
        g_tconf[pos] = conf;
        g_tlab[pos]  = (float)(int)g_label[idx];
        float mv = fmaxf(fmaxf(bx.x, bx.y), fmaxf(bx.z, bx.w));
        atomicMax(&g_maxc, __float_as_uint(mv));   // coords >= 0 -> bit-monotone
    }
}

// ---------------- K5: offsets + IoU bitmask + last-block NMS + output ----------------
__global__ __launch_bounds__(256) void k5_iou_nms_out(float* __restrict__ out) {
    __shared__ float4 soff[TOPK];
    __shared__ float sarea[TOPK];
    __shared__ u32 skeep[32];
    __shared__ u32 sLast;
    int tid = threadIdx.x;  // 256
    float mc = __fadd_rn(__uint_as_float(g_maxc), 1.0f);
    for (int i = tid; i < TOPK; i += 256) {
        float4 bx = g_tbox[i];
        float tt = __fmul_rn(g_tlab[i], mc);
        float ox1 = __fadd_rn(bx.x, tt), oy1 = __fadd_rn(bx.y, tt);
        float ox2 = __fadd_rn(bx.z, tt), oy2 = __fadd_rn(bx.w, tt);
        soff[i]  = make_float4(ox1, oy1, ox2, oy2);
        sarea[i] = __fmul_rn(__fsub_rn(ox2, ox1), __fsub_rn(oy2, oy1));
    }
    __syncthreads();
    int wid = tid >> 5, lane = tid & 31;
    int i = blockIdx.x * 8 + wid;
    float4 bi = soff[i];
    float  ai = sarea[i];
    u32 word = 0;
    int jbase = lane * 32;
    #pragma unroll 4
    for (int jj = 0; jj < 32; jj++) {
        int j = jbase + jj;
        float4 bj = soff[j];
        float lx = fmaxf(bi.x, bj.x), ly = fmaxf(bi.y, bj.y);
        float rx = fminf(bi.z, bj.z), ry = fminf(bi.w, bj.w);
        float wx = fmaxf(__fsub_rn(rx, lx), 0.0f);
        float wy = fmaxf(__fsub_rn(ry, ly), 0.0f);
        float inter = __fmul_rn(wx, wy);
        float un = __fsub_rn(__fadd_rn(ai, sarea[j]), inter);
        float iou = __fdiv_rn(inter, fmaxf(un, 1e-9f));
        if (j > i && iou > 0.6f) word |= (1u << jj);
    }
    g_sup[i * 32 + lane] = word;
    bool nzr = __any_sync(FULLM, word != 0u);
    if (lane == 0) g_rownz[i] = nzr ? (u8)1 : (u8)0;
    __threadfence();
    if (tid == 0) sLast = (atomicAdd(&g_tick[2], 1u) == gridDim.x - 1) ? 1u : 0u;
    __syncthreads();
    if (!sLast) return;
    if (tid == 0) { g_tick[2] = 0u; g_cnt[0] = 0u; g_cnt[1] = 0u; g_maxc = 0u; } // self-clean
    // --- single-warp exact sequential greedy NMS (warp 0) ---
    if (tid < 32) {
        u32 kw = 0;
        #pragma unroll 8
        for (int j = 0; j < 32; j++)
            kw |= (g_tconf[tid * 32 + j] >= 0.5f) ? (1u << j) : 0u;
        u32 nz = 0;
        const u32* rp = (const u32*)g_rownz;
        #pragma unroll
        for (int q = 0; q < 8; q++) {
            u32 v = rp[tid * 8 + q];
            u32 bitsv = (v & 1u) | (((v >> 8) & 1u) << 1) |
                        (((v >> 16) & 1u) << 2) | (((v >> 24) & 1u) << 3);
            nz |= bitsv << (4 * q);
        }
        for (int g = 0; g < 32; g++) {
            u32 nzg = __shfl_sync(FULLM, nz, g);
            if (!nzg) continue;
            u32 kwg = __shfl_sync(FULLM, kw, g);
            u32 act = nzg & kwg;
            while (act) {
                int b = __ffs(act) - 1;
                int r = g * 32 + b;
                kw &= ~g_sup[r * 32 + tid];
                kwg = __shfl_sync(FULLM, kw, g);
                u32 maskAbove = (b == 31) ? 0u : (FULLM << (b + 1));
                act = nzg & kwg & maskAbove;
            }
        }
        skeep[tid] = kw;
    }
    __syncthreads();
    // --- output: 256 threads x 4 rows ---
    #pragma unroll
    for (int q = 0; q < 4; q++) {
        int k = tid * 4 + q;
        bool kp = (skeep[k >> 5] >> (k & 31)) & 1u;
        float2* o = (float2*)(out + (size_t)k * 6);
        if (kp) {
            float4 b = g_tbox[k];
            o[0] = make_float2(b.x, b.y);
            o[1] = make_float2(b.z, b.w);
            o[2] = make_float2(g_tconf[k], g_tlab[k]);
        } else {
            float2 z = make_float2(0.f, 0.f);
            o[0] = z; o[1] = z; o[2] = z;
        }
    }
}

// ---------------- launch ----------------
extern "C" void kernel_launch(void* const* d_in, const int* in_sizes, int n_in,
                              void* d_out, int out_size) {
    const float* boxes  = (const float*)d_in[0];
    const float* scores = (const float*)d_in[1];
    if (in_sizes[0] != N_ANCH * 4) {  // defensive input-order check
        boxes  = (const float*)d_in[1];
        scores = (const float*)d_in[0];
    }
    float* out = (float*)d_out;

    k1_argmax<<<1184, 256>>>(scores);
    k2_hist<<<512, 256>>>();
    k3_gather<<<N_ANCH / 256, 256>>>();
    k4_rank<<<(TOPK + BND_CAP) / 8, 256>>>((const float4*)boxes);
    k5_iou_nms_out<<<TOPK / 8, 256>>>(out);
}